// round 1
// baseline (speedup 1.0000x reference)
#include <cuda_runtime.h>
#include <cuda_bf16.h>
#include <cstdint>
#include <cstddef>

// Problem constants
#define BATCH   8
#define SEQ     4096
#define DMODEL  1024
#define NHEAD   16
#define DHEAD   64
#define TOKENS  (BATCH * SEQ)            // 32768

// Scratch (no cudaMalloc allowed): 4 x 128 MB static device buffers
__device__ float g_q  [(size_t)TOKENS * DMODEL];
__device__ float g_k  [(size_t)TOKENS * DMODEL];
__device__ float g_v  [(size_t)TOKENS * DMODEL];
__device__ float g_ctx[(size_t)TOKENS * DMODEL];

// ---------------------------------------------------------------------------
// GEMM: C[M,N] = A[M,K] @ W[N,K]^T + bias[N]
// A row-major [M,K], W row-major [N,K] (torch Linear weight), both K-major:
// coalesced float4 loads on both operands.
// Tile 128x128x16, 256 threads, 8x8 per-thread microtile (split-4 layout).
// ---------------------------------------------------------------------------
#define BM 128
#define BN 128
#define BK 16

__global__ __launch_bounds__(256, 2) void sgemm_bias_kernel(
    const float* __restrict__ A, const float* __restrict__ W,
    const float* __restrict__ bias, float* __restrict__ C,
    int M, int N, int K)
{
    __shared__ float As[BK][BM];
    __shared__ float Ws[BK][BN];

    const int tid = threadIdx.x;
    const int tx  = tid & 15;   // -> N direction
    const int ty  = tid >> 4;   // -> M direction

    const float* Ab = A + (size_t)blockIdx.y * BM * K;
    const float* Wb = W + (size_t)blockIdx.x * BN * K;

    const int lrow = tid >> 2;        // 0..63
    const int lcol = (tid & 3) * 4;   // 0,4,8,12

    float acc[8][8];
#pragma unroll
    for (int i = 0; i < 8; i++)
#pragma unroll
        for (int j = 0; j < 8; j++) acc[i][j] = 0.f;

    for (int k0 = 0; k0 < K; k0 += BK) {
        // Load 128x16 A tile and 128x16 W tile (each thread: 2 float4 per tile)
#pragma unroll
        for (int r = 0; r < 2; r++) {
            const int row = lrow + r * 64;
            float4 va = *reinterpret_cast<const float4*>(Ab + (size_t)row * K + k0 + lcol);
            As[lcol + 0][row] = va.x;
            As[lcol + 1][row] = va.y;
            As[lcol + 2][row] = va.z;
            As[lcol + 3][row] = va.w;
            float4 vw = *reinterpret_cast<const float4*>(Wb + (size_t)row * K + k0 + lcol);
            Ws[lcol + 0][row] = vw.x;
            Ws[lcol + 1][row] = vw.y;
            Ws[lcol + 2][row] = vw.z;
            Ws[lcol + 3][row] = vw.w;
        }
        __syncthreads();

#pragma unroll
        for (int kk = 0; kk < BK; kk++) {
            float a[8], w[8];
            *reinterpret_cast<float4*>(&a[0]) = *reinterpret_cast<const float4*>(&As[kk][ty * 4]);
            *reinterpret_cast<float4*>(&a[4]) = *reinterpret_cast<const float4*>(&As[kk][ty * 4 + 64]);
            *reinterpret_cast<float4*>(&w[0]) = *reinterpret_cast<const float4*>(&Ws[kk][tx * 4]);
            *reinterpret_cast<float4*>(&w[4]) = *reinterpret_cast<const float4*>(&Ws[kk][tx * 4 + 64]);
#pragma unroll
            for (int i = 0; i < 8; i++)
#pragma unroll
                for (int j = 0; j < 8; j++)
                    acc[i][j] = fmaf(a[i], w[j], acc[i][j]);
        }
        __syncthreads();
    }

    // Epilogue: add bias, write float4s
#pragma unroll
    for (int i = 0; i < 8; i++) {
        const int ri  = (i < 4) ? (ty * 4 + i) : (64 + ty * 4 + (i - 4));
        const int row = blockIdx.y * BM + ri;
#pragma unroll
        for (int j4 = 0; j4 < 2; j4++) {
            const int col = blockIdx.x * BN + tx * 4 + j4 * 64;
            float4 o;
            o.x = acc[i][j4 * 4 + 0] + bias[col + 0];
            o.y = acc[i][j4 * 4 + 1] + bias[col + 1];
            o.z = acc[i][j4 * 4 + 2] + bias[col + 2];
            o.w = acc[i][j4 * 4 + 3] + bias[col + 3];
            *reinterpret_cast<float4*>(C + (size_t)row * N + col) = o;
        }
    }
}

// ---------------------------------------------------------------------------
// Per-token attention: scores[h][g] = q[h,:].k[g,:]/8, softmax over g,
// ctx[h][d] = sum_g p[h][g] * v[g][d].  One block (256 thr) per token.
// ---------------------------------------------------------------------------
__global__ __launch_bounds__(256) void attn_kernel(
    const float* __restrict__ Q, const float* __restrict__ K,
    const float* __restrict__ V, float* __restrict__ CTX)
{
    const size_t base = (size_t)blockIdx.x * DMODEL;
    __shared__ float sq[DMODEL];
    __shared__ float sk[DMODEL];
    __shared__ float sv[DMODEL];
    __shared__ float sp[NHEAD][NHEAD];

    const int tid = threadIdx.x;
#pragma unroll
    for (int i = tid; i < DMODEL; i += 256) {
        sq[i] = Q[base + i];
        sk[i] = K[base + i];
        sv[i] = V[base + i];
    }
    __syncthreads();

    // one score per thread: (h,g) = (tid/16, tid%16)
    const int h = tid >> 4;
    const int g = tid & 15;
    const int rot = tid & 31;   // rotate d to avoid stride-64 bank conflicts
    float s = 0.f;
#pragma unroll
    for (int dd = 0; dd < DHEAD; dd++) {
        const int d = (dd + rot) & (DHEAD - 1);
        s = fmaf(sq[h * DHEAD + d], sk[g * DHEAD + d], s);
    }
    s *= 0.125f;  // 1/sqrt(64)

    // softmax over g: 16-lane shuffle groups
    float m = s;
#pragma unroll
    for (int o = 8; o > 0; o >>= 1) m = fmaxf(m, __shfl_xor_sync(0xFFFFFFFFu, m, o, 16));
    const float e = __expf(s - m);
    float sum = e;
#pragma unroll
    for (int o = 8; o > 0; o >>= 1) sum += __shfl_xor_sync(0xFFFFFFFFu, sum, o, 16);
    sp[h][g] = e / sum;
    __syncthreads();

    // ctx: 4 outputs per thread
#pragma unroll
    for (int r = 0; r < 4; r++) {
        const int idx = tid + r * 256;
        const int hh  = idx >> 6;
        const int d   = idx & (DHEAD - 1);
        float acc = 0.f;
#pragma unroll
        for (int gg = 0; gg < NHEAD; gg++)
            acc = fmaf(sp[hh][gg], sv[gg * DHEAD + d], acc);
        CTX[base + idx] = acc;
    }
}

// ---------------------------------------------------------------------------
extern "C" void kernel_launch(void* const* d_in, const int* in_sizes, int n_in,
                              void* d_out, int out_size)
{
    const float* x  = (const float*)d_in[0];
    const float* wq = (const float*)d_in[1];
    const float* bq = (const float*)d_in[2];
    const float* wk = (const float*)d_in[3];
    const float* bk = (const float*)d_in[4];
    const float* wv = (const float*)d_in[5];
    const float* bv = (const float*)d_in[6];
    const float* wo = (const float*)d_in[7];
    const float* bo = (const float*)d_in[8];
    float* out = (float*)d_out;

    float *q, *k, *v, *ctx;
    cudaGetSymbolAddress((void**)&q,   g_q);
    cudaGetSymbolAddress((void**)&k,   g_k);
    cudaGetSymbolAddress((void**)&v,   g_v);
    cudaGetSymbolAddress((void**)&ctx, g_ctx);

    const int M = TOKENS, N = DMODEL, K = DMODEL;
    dim3 ggrid(N / BN, M / BM);   // (8, 256)
    dim3 gblk(256);

    sgemm_bias_kernel<<<ggrid, gblk>>>(x, wq, bq, q, M, N, K);
    sgemm_bias_kernel<<<ggrid, gblk>>>(x, wk, bk, k, M, N, K);
    sgemm_bias_kernel<<<ggrid, gblk>>>(x, wv, bv, v, M, N, K);

    attn_kernel<<<TOKENS, 256>>>(q, k, v, ctx);

    sgemm_bias_kernel<<<ggrid, gblk>>>(ctx, wo, bo, out, M, N, K);
}

// round 3
// speedup vs baseline: 2.7469x; 2.7469x over previous
#include <cuda_runtime.h>
#include <cuda_bf16.h>
#include <cstdint>
#include <cstddef>

// Problem constants
#define BATCH   8
#define SEQ     4096
#define DMODEL  1024
#define NHEAD   16
#define DHEAD   64
#define TOKENS  (BATCH * SEQ)            // 32768
#define GK      DMODEL                   // GEMM K = 1024

// ---------------------------------------------------------------------------
// Static scratch (no cudaMalloc allowed)
// ---------------------------------------------------------------------------
__device__ float g_q  [(size_t)TOKENS * DMODEL];
__device__ float g_k  [(size_t)TOKENS * DMODEL];
__device__ float g_v  [(size_t)TOKENS * DMODEL];

__device__ __nv_bfloat16 g_xhi[(size_t)TOKENS * DMODEL];
__device__ __nv_bfloat16 g_xlo[(size_t)TOKENS * DMODEL];
__device__ __nv_bfloat16 g_chi[(size_t)TOKENS * DMODEL];
__device__ __nv_bfloat16 g_clo[(size_t)TOKENS * DMODEL];

__device__ __nv_bfloat16 g_whi[4][(size_t)DMODEL * DMODEL];
__device__ __nv_bfloat16 g_wlo[4][(size_t)DMODEL * DMODEL];

// ---------------------------------------------------------------------------
__device__ __forceinline__ uint32_t smem_u32(const void* p) {
    uint32_t a;
    asm("{ .reg .u64 t; cvta.to.shared.u64 t, %1; cvt.u32.u64 %0, t; }"
        : "=r"(a) : "l"(p));
    return a;
}

__device__ __forceinline__ void ldsm_x4(uint32_t (&r)[4], uint32_t addr) {
    asm volatile("ldmatrix.sync.aligned.m8n8.x4.shared.b16 {%0,%1,%2,%3}, [%4];"
                 : "=r"(r[0]), "=r"(r[1]), "=r"(r[2]), "=r"(r[3]) : "r"(addr));
}

__device__ __forceinline__ void mma_bf16(float (&d)[4], const uint32_t (&a)[4],
                                         const uint32_t* b) {
    asm volatile(
        "mma.sync.aligned.m16n8k16.row.col.f32.bf16.bf16.f32 "
        "{%0,%1,%2,%3}, {%4,%5,%6,%7}, {%8,%9}, {%0,%1,%2,%3};"
        : "+f"(d[0]), "+f"(d[1]), "+f"(d[2]), "+f"(d[3])
        : "r"(a[0]), "r"(a[1]), "r"(a[2]), "r"(a[3]), "r"(b[0]), "r"(b[1]));
}

__device__ __forceinline__ void cp16(uint32_t dst, const void* src) {
    asm volatile("cp.async.cg.shared.global [%0], [%1], 16;"
                 :: "r"(dst), "l"(src));
}

// ---------------------------------------------------------------------------
// Split fp32 -> (bf16 hi, bf16 lo)
// ---------------------------------------------------------------------------
__global__ void split_kernel(const float* __restrict__ src,
                             __nv_bfloat16* __restrict__ hi,
                             __nv_bfloat16* __restrict__ lo, int n4) {
    int i = blockIdx.x * blockDim.x + threadIdx.x;
    if (i >= n4) return;
    float4 v = reinterpret_cast<const float4*>(src)[i];
    __nv_bfloat16 h[4], l[4];
    float vv[4] = {v.x, v.y, v.z, v.w};
#pragma unroll
    for (int j = 0; j < 4; j++) {
        h[j] = __float2bfloat16_rn(vv[j]);
        l[j] = __float2bfloat16_rn(vv[j] - __bfloat162float(h[j]));
    }
    reinterpret_cast<uint2*>(hi)[i] = *reinterpret_cast<uint2*>(h);
    reinterpret_cast<uint2*>(lo)[i] = *reinterpret_cast<uint2*>(l);
}

// ---------------------------------------------------------------------------
// HMMA GEMM: C[M,1024] = A @ W^T + bias, bf16x3 decomposition.
// CTA tile 128x128, K-chunk 64, double-buffered cp.async.
// 8 warps (4 in M x 2 in N), warp tile 32x64. mma.sync m16n8k16 bf16.
// SMEM tiles: 128 rows x 128B, SW128 xor swizzle (conflict-free ldmatrix).
// ---------------------------------------------------------------------------
#define CHUNK       64
#define NCHUNK      (GK / CHUNK)        // 16
#define TILE_BYTES  16384               // 128 x 128B
#define STAGE_BYTES (4 * TILE_BYTES)    // Ahi, Alo, Whi, Wlo
#define SMEM_DYN    (2 * STAGE_BYTES)   // 131072

__global__ __launch_bounds__(256, 1) void gemm_bf16x3(
    const __nv_bfloat16* __restrict__ Ahi, const __nv_bfloat16* __restrict__ Alo,
    const __nv_bfloat16* __restrict__ Whi, const __nv_bfloat16* __restrict__ Wlo,
    const float* __restrict__ bias, float* __restrict__ C)
{
    extern __shared__ __align__(1024) char smem[];
    const uint32_t sb = smem_u32(smem);
    const int tid  = threadIdx.x;
    const int wid  = tid >> 5;
    const int lane = tid & 31;
    const int wm   = wid & 3;          // warp row (M)
    const int wn   = wid >> 2;         // warp col (N)

    const size_t rowM0 = (size_t)blockIdx.y * 128;
    const int    colN0 = blockIdx.x * 128;

    const char* srcs[4] = {
        (const char*)(Ahi + rowM0 * GK), (const char*)(Alo + rowM0 * GK),
        (const char*)(Whi + (size_t)colN0 * GK), (const char*)(Wlo + (size_t)colN0 * GK)
    };

    // ldmatrix per-lane base indices
    const int a_row = wm * 32 + (lane & 15);           // + mi*16
    const int a_ku  = lane >> 4;                       // k halves (units)
    const int b_row = wn * 64 + (lane & 7) + ((lane >> 4) << 3);  // + g*16
    const int b_ku  = (lane >> 3) & 1;

    float acc[2][8][4];
#pragma unroll
    for (int mi = 0; mi < 2; mi++)
#pragma unroll
        for (int nf = 0; nf < 8; nf++)
#pragma unroll
            for (int j = 0; j < 4; j++) acc[mi][nf][j] = 0.f;

    // async loader: 16 x 16B per thread per chunk
    auto load_chunk = [&](int c) {
        const int s = c & 1;
        const uint32_t stage = sb + s * STAGE_BYTES;
        const int k0b = c * CHUNK * 2;       // byte offset in K
#pragma unroll
        for (int u2 = 0; u2 < 16; u2++) {
            const int g   = tid + u2 * 256;  // 0..4095
            const int t   = g >> 10;
            const int w   = g & 1023;
            const int row = w >> 3;
            const int u   = w & 7;
            const uint32_t dst = stage + t * TILE_BYTES + row * 128
                               + ((u ^ (row & 7)) << 4);
            cp16(dst, srcs[t] + (size_t)row * 2048 + k0b + u * 16);
        }
        asm volatile("cp.async.commit_group;" ::: "memory");
    };

    load_chunk(0);

    for (int c = 0; c < NCHUNK; c++) {
        if (c + 1 < NCHUNK) {
            load_chunk(c + 1);
            asm volatile("cp.async.wait_group 1;" ::: "memory");
        } else {
            asm volatile("cp.async.wait_group 0;" ::: "memory");
        }
        __syncthreads();

        const uint32_t stage = sb + (c & 1) * STAGE_BYTES;
        const uint32_t t_ahi = stage;
        const uint32_t t_alo = stage + TILE_BYTES;
        const uint32_t t_whi = stage + 2 * TILE_BYTES;
        const uint32_t t_wlo = stage + 3 * TILE_BYTES;

#pragma unroll
        for (int ks = 0; ks < 4; ks++) {
            // A fragments (hi & lo), 2 m16 tiles
            uint32_t ahi[2][4], alo[2][4];
#pragma unroll
            for (int mi = 0; mi < 2; mi++) {
                const int row = a_row + mi * 16;
                const int u   = ks * 2 + a_ku;
                const uint32_t off = row * 128 + ((u ^ (row & 7)) << 4);
                ldsm_x4(ahi[mi], t_ahi + off);
                ldsm_x4(alo[mi], t_alo + off);
            }
            // B fragments (hi & lo), 4 n16 groups -> 8 n8 frags
            uint32_t bhi[4][4], blo[4][4];
#pragma unroll
            for (int gg = 0; gg < 4; gg++) {
                const int row = b_row + gg * 16;
                const int u   = ks * 2 + b_ku;
                const uint32_t off = row * 128 + ((u ^ (row & 7)) << 4);
                ldsm_x4(bhi[gg], t_whi + off);
                ldsm_x4(blo[gg], t_wlo + off);
            }
#pragma unroll
            for (int mi = 0; mi < 2; mi++)
#pragma unroll
                for (int gg = 0; gg < 4; gg++)
#pragma unroll
                    for (int sub = 0; sub < 2; sub++) {
                        const int nf = gg * 2 + sub;
                        mma_bf16(acc[mi][nf], ahi[mi], &bhi[gg][sub * 2]);
                        mma_bf16(acc[mi][nf], ahi[mi], &blo[gg][sub * 2]);
                        mma_bf16(acc[mi][nf], alo[mi], &bhi[gg][sub * 2]);
                    }
        }
        __syncthreads();
    }

    // Epilogue: add bias, write float2 per (mi, nf, rowhalf)
#pragma unroll
    for (int mi = 0; mi < 2; mi++) {
#pragma unroll
        for (int nf = 0; nf < 8; nf++) {
            const int col = colN0 + wn * 64 + nf * 8 + (lane & 3) * 2;
            const float2 bv = *reinterpret_cast<const float2*>(bias + col);
#pragma unroll
            for (int rh = 0; rh < 2; rh++) {
                const size_t row = rowM0 + wm * 32 + mi * 16 + (lane >> 2) + rh * 8;
                float2 o;
                o.x = acc[mi][nf][rh * 2 + 0] + bv.x;
                o.y = acc[mi][nf][rh * 2 + 1] + bv.y;
                *reinterpret_cast<float2*>(C + row * DMODEL + col) = o;
            }
        }
    }
}

// ---------------------------------------------------------------------------
// Per-token attention; writes ctx directly as bf16 hi/lo (skips a split pass)
// ---------------------------------------------------------------------------
__global__ __launch_bounds__(256) void attn_kernel(
    const float* __restrict__ Q, const float* __restrict__ K,
    const float* __restrict__ V,
    __nv_bfloat16* __restrict__ CHI, __nv_bfloat16* __restrict__ CLO)
{
    const size_t base = (size_t)blockIdx.x * DMODEL;
    __shared__ float sq[DMODEL];
    __shared__ float sk[DMODEL];
    __shared__ float sv[DMODEL];
    __shared__ float sp[NHEAD][NHEAD];

    const int tid = threadIdx.x;
#pragma unroll
    for (int i = tid; i < DMODEL; i += 256) {
        sq[i] = Q[base + i];
        sk[i] = K[base + i];
        sv[i] = V[base + i];
    }
    __syncthreads();

    const int h = tid >> 4;
    const int g = tid & 15;
    const int rot = tid & 31;
    float s = 0.f;
#pragma unroll
    for (int dd = 0; dd < DHEAD; dd++) {
        const int d = (dd + rot) & (DHEAD - 1);
        s = fmaf(sq[h * DHEAD + d], sk[g * DHEAD + d], s);
    }
    s *= 0.125f;

    float m = s;
#pragma unroll
    for (int o = 8; o > 0; o >>= 1) m = fmaxf(m, __shfl_xor_sync(0xFFFFFFFFu, m, o, 16));
    const float e = __expf(s - m);
    float sum = e;
#pragma unroll
    for (int o = 8; o > 0; o >>= 1) sum += __shfl_xor_sync(0xFFFFFFFFu, sum, o, 16);
    sp[h][g] = e / sum;
    __syncthreads();

#pragma unroll
    for (int r = 0; r < 4; r++) {
        const int idx = tid + r * 256;
        const int hh  = idx >> 6;
        const int d   = idx & (DHEAD - 1);
        float a = 0.f;
#pragma unroll
        for (int gg = 0; gg < NHEAD; gg++)
            a = fmaf(sp[hh][gg], sv[gg * DHEAD + d], a);
        __nv_bfloat16 hi = __float2bfloat16_rn(a);
        __nv_bfloat16 lo = __float2bfloat16_rn(a - __bfloat162float(hi));
        CHI[base + idx] = hi;
        CLO[base + idx] = lo;
    }
}

// ---------------------------------------------------------------------------
extern "C" void kernel_launch(void* const* d_in, const int* in_sizes, int n_in,
                              void* d_out, int out_size)
{
    const float* x  = (const float*)d_in[0];
    const float* wq = (const float*)d_in[1];
    const float* bq = (const float*)d_in[2];
    const float* wk = (const float*)d_in[3];
    const float* bk = (const float*)d_in[4];
    const float* wv = (const float*)d_in[5];
    const float* bv = (const float*)d_in[6];
    const float* wo = (const float*)d_in[7];
    const float* bo = (const float*)d_in[8];
    float* out = (float*)d_out;

    float *q, *k, *v;
    cudaGetSymbolAddress((void**)&q, g_q);
    cudaGetSymbolAddress((void**)&k, g_k);
    cudaGetSymbolAddress((void**)&v, g_v);

    __nv_bfloat16 *xhi, *xlo, *chi, *clo, *whi, *wlo;
    cudaGetSymbolAddress((void**)&xhi, g_xhi);
    cudaGetSymbolAddress((void**)&xlo, g_xlo);
    cudaGetSymbolAddress((void**)&chi, g_chi);
    cudaGetSymbolAddress((void**)&clo, g_clo);
    cudaGetSymbolAddress((void**)&whi, g_whi);
    cudaGetSymbolAddress((void**)&wlo, g_wlo);

    cudaFuncSetAttribute(gemm_bf16x3,
                         cudaFuncAttributeMaxDynamicSharedMemorySize, SMEM_DYN);

    const size_t WN = (size_t)DMODEL * DMODEL;
    const int nx4 = (TOKENS * DMODEL) / 4;
    const int nw4 = (int)(WN / 4);

    split_kernel<<<(nx4 + 255) / 256, 256>>>(x, xhi, xlo, nx4);
    split_kernel<<<(nw4 + 255) / 256, 256>>>(wq, whi + 0 * WN, wlo + 0 * WN, nw4);
    split_kernel<<<(nw4 + 255) / 256, 256>>>(wk, whi + 1 * WN, wlo + 1 * WN, nw4);
    split_kernel<<<(nw4 + 255) / 256, 256>>>(wv, whi + 2 * WN, wlo + 2 * WN, nw4);
    split_kernel<<<(nw4 + 255) / 256, 256>>>(wo, whi + 3 * WN, wlo + 3 * WN, nw4);

    dim3 ggrid(DMODEL / 128, TOKENS / 128);   // (8, 256)
    gemm_bf16x3<<<ggrid, 256, SMEM_DYN>>>(xhi, xlo, whi + 0 * WN, wlo + 0 * WN, bq, q);
    gemm_bf16x3<<<ggrid, 256, SMEM_DYN>>>(xhi, xlo, whi + 1 * WN, wlo + 1 * WN, bk, k);
    gemm_bf16x3<<<ggrid, 256, SMEM_DYN>>>(xhi, xlo, whi + 2 * WN, wlo + 2 * WN, bv, v);

    attn_kernel<<<TOKENS, 256>>>(q, k, v, chi, clo);

    gemm_bf16x3<<<ggrid, 256, SMEM_DYN>>>(chi, clo, whi + 3 * WN, wlo + 3 * WN, bo, out);
}

// round 5
// speedup vs baseline: 3.7189x; 1.3539x over previous
#include <cuda_runtime.h>
#include <cuda_fp16.h>
#include <cstdint>
#include <cstddef>

// Problem constants
#define BATCH   8
#define SEQ     4096
#define DMODEL  1024
#define NHEAD   16
#define DHEAD   64
#define TOKENS  (BATCH * SEQ)            // 32768
#define GK      DMODEL                   // GEMM K = 1024

// ---------------------------------------------------------------------------
// Static scratch (no cudaMalloc allowed)
// ---------------------------------------------------------------------------
__device__ float g_q  [(size_t)TOKENS * DMODEL];
__device__ float g_k  [(size_t)TOKENS * DMODEL];
__device__ float g_v  [(size_t)TOKENS * DMODEL];

__device__ __half g_xh [(size_t)TOKENS * DMODEL];
__device__ __half g_ch [(size_t)TOKENS * DMODEL];

__device__ __half g_whi[4][(size_t)DMODEL * DMODEL];
__device__ __half g_wlo[4][(size_t)DMODEL * DMODEL];

// ---------------------------------------------------------------------------
__device__ __forceinline__ uint32_t smem_u32(const void* p) {
    uint32_t a;
    asm("{ .reg .u64 t; cvta.to.shared.u64 t, %1; cvt.u32.u64 %0, t; }"
        : "=r"(a) : "l"(p));
    return a;
}

__device__ __forceinline__ void ldsm_x4(uint32_t (&r)[4], uint32_t addr) {
    asm volatile("ldmatrix.sync.aligned.m8n8.x4.shared.b16 {%0,%1,%2,%3}, [%4];"
                 : "=r"(r[0]), "=r"(r[1]), "=r"(r[2]), "=r"(r[3]) : "r"(addr));
}

__device__ __forceinline__ void mma_f16(float (&d)[4], const uint32_t (&a)[4],
                                        const uint32_t* b) {
    asm volatile(
        "mma.sync.aligned.m16n8k16.row.col.f32.f16.f16.f32 "
        "{%0,%1,%2,%3}, {%4,%5,%6,%7}, {%8,%9}, {%0,%1,%2,%3};"
        : "+f"(d[0]), "+f"(d[1]), "+f"(d[2]), "+f"(d[3])
        : "r"(a[0]), "r"(a[1]), "r"(a[2]), "r"(a[3]), "r"(b[0]), "r"(b[1]));
}

__device__ __forceinline__ void cp16(uint32_t dst, const void* src) {
    asm volatile("cp.async.cg.shared.global [%0], [%1], 16;"
                 :: "r"(dst), "l"(src));
}

// ---------------------------------------------------------------------------
// x (fp32) -> fp16 (round-to-nearest), vectorized
// ---------------------------------------------------------------------------
__global__ void conv_f16(const float* __restrict__ src,
                         __half* __restrict__ dst, int n4) {
    int i = blockIdx.x * blockDim.x + threadIdx.x;
    if (i >= n4) return;
    float4 v = reinterpret_cast<const float4*>(src)[i];
    __half h[4] = { __float2half_rn(v.x), __float2half_rn(v.y),
                    __float2half_rn(v.z), __float2half_rn(v.w) };
    reinterpret_cast<uint2*>(dst)[i] = *reinterpret_cast<uint2*>(h);
}

// Weights: fp32 -> (fp16 hi, fp16 lo)
__global__ void split_f16(const float* __restrict__ src,
                          __half* __restrict__ hi,
                          __half* __restrict__ lo, int n4) {
    int i = blockIdx.x * blockDim.x + threadIdx.x;
    if (i >= n4) return;
    float4 v = reinterpret_cast<const float4*>(src)[i];
    float vv[4] = {v.x, v.y, v.z, v.w};
    __half h[4], l[4];
#pragma unroll
    for (int j = 0; j < 4; j++) {
        h[j] = __float2half_rn(vv[j]);
        l[j] = __float2half_rn(vv[j] - __half2float(h[j]));
    }
    reinterpret_cast<uint2*>(hi)[i] = *reinterpret_cast<uint2*>(h);
    reinterpret_cast<uint2*>(lo)[i] = *reinterpret_cast<uint2*>(l);
}

// ---------------------------------------------------------------------------
// HMMA GEMM: C[M,1024] = Ah @ (Whi + Wlo)^T + bias   (fp16x2, 2 products)
// CTA tile 128x128, K-chunk 64, 3-stage cp.async pipeline.
// 8 warps (4 in M x 2 in N), warp tile 32x64. mma.sync m16n8k16 f16.
// SMEM tiles: 128 rows x 128B, SW128 xor swizzle (conflict-free ldmatrix).
// ---------------------------------------------------------------------------
#define CHUNK       64
#define NCHUNK      (GK / CHUNK)        // 16
#define TILE_BYTES  16384               // 128 x 128B
#define STAGE_BYTES (3 * TILE_BYTES)    // Ah, Whi, Wlo = 49152
#define NSTAGE      3
#define SMEM_DYN    (NSTAGE * STAGE_BYTES)  // 147456

__global__ __launch_bounds__(256, 1) void gemm_f16x2(
    const __half* __restrict__ Ah,
    const __half* __restrict__ Whi, const __half* __restrict__ Wlo,
    const float* __restrict__ bias, float* __restrict__ C)
{
    extern __shared__ __align__(1024) char smem[];
    const uint32_t sb = smem_u32(smem);
    const int tid  = threadIdx.x;
    const int wid  = tid >> 5;
    const int lane = tid & 31;
    const int wm   = wid & 3;          // warp row (M)
    const int wn   = wid >> 2;         // warp col (N)

    const size_t rowM0 = (size_t)blockIdx.y * 128;
    const int    colN0 = blockIdx.x * 128;

    const char* srcs[3] = {
        (const char*)(Ah  + rowM0 * GK),
        (const char*)(Whi + (size_t)colN0 * GK),
        (const char*)(Wlo + (size_t)colN0 * GK)
    };

    // ldmatrix per-lane base indices
    const int a_row = wm * 32 + (lane & 15);                      // + mi*16
    const int a_ku  = lane >> 4;
    const int b_row = wn * 64 + (lane & 7) + ((lane >> 4) << 3);  // + g*16
    const int b_ku  = (lane >> 3) & 1;

    float acc[2][8][4];
#pragma unroll
    for (int mi = 0; mi < 2; mi++)
#pragma unroll
        for (int nf = 0; nf < 8; nf++)
#pragma unroll
            for (int j = 0; j < 4; j++) acc[mi][nf][j] = 0.f;

    // async loader: 12 x 16B per thread per chunk (3 tiles x 1024 units)
    auto load_chunk = [&](int c) {
        const uint32_t stage = sb + (c % NSTAGE) * STAGE_BYTES;
        const int k0b = c * CHUNK * 2;       // byte offset along K
#pragma unroll
        for (int u2 = 0; u2 < 12; u2++) {
            const int g   = tid + u2 * 256;  // 0..3071
            const int t   = g >> 10;
            const int w   = g & 1023;
            const int row = w >> 3;
            const int u   = w & 7;
            const uint32_t dst = stage + t * TILE_BYTES + row * 128
                               + ((u ^ (row & 7)) << 4);
            cp16(dst, srcs[t] + (size_t)row * 2048 + k0b + u * 16);
        }
        asm volatile("cp.async.commit_group;" ::: "memory");
    };

    load_chunk(0);
    load_chunk(1);

    for (int c = 0; c < NCHUNK; c++) {
        if (c + 2 < NCHUNK) {
            load_chunk(c + 2);
            asm volatile("cp.async.wait_group 2;" ::: "memory");
        } else if (c + 1 < NCHUNK) {
            asm volatile("cp.async.wait_group 1;" ::: "memory");
        } else {
            asm volatile("cp.async.wait_group 0;" ::: "memory");
        }
        __syncthreads();

        const uint32_t stage = sb + (c % NSTAGE) * STAGE_BYTES;
        const uint32_t t_ah  = stage;
        const uint32_t t_whi = stage + TILE_BYTES;
        const uint32_t t_wlo = stage + 2 * TILE_BYTES;

#pragma unroll
        for (int ks = 0; ks < 4; ks++) {
            uint32_t ah[2][4];
#pragma unroll
            for (int mi = 0; mi < 2; mi++) {
                const int row = a_row + mi * 16;
                const int u   = ks * 2 + a_ku;
                const uint32_t off = row * 128 + ((u ^ (row & 7)) << 4);
                ldsm_x4(ah[mi], t_ah + off);
            }
            uint32_t bhi[4][4], blo[4][4];
#pragma unroll
            for (int gg = 0; gg < 4; gg++) {
                const int row = b_row + gg * 16;
                const int u   = ks * 2 + b_ku;
                const uint32_t off = row * 128 + ((u ^ (row & 7)) << 4);
                ldsm_x4(bhi[gg], t_whi + off);
                ldsm_x4(blo[gg], t_wlo + off);
            }
#pragma unroll
            for (int mi = 0; mi < 2; mi++)
#pragma unroll
                for (int gg = 0; gg < 4; gg++)
#pragma unroll
                    for (int sub = 0; sub < 2; sub++) {
                        const int nf = gg * 2 + sub;
                        mma_f16(acc[mi][nf], ah[mi], &bhi[gg][sub * 2]);
                        mma_f16(acc[mi][nf], ah[mi], &blo[gg][sub * 2]);
                    }
        }
        __syncthreads();
    }

    // Epilogue: add bias, write float2 per (mi, nf, rowhalf)
#pragma unroll
    for (int mi = 0; mi < 2; mi++) {
#pragma unroll
        for (int nf = 0; nf < 8; nf++) {
            const int col = colN0 + wn * 64 + nf * 8 + (lane & 3) * 2;
            const float2 bv = *reinterpret_cast<const float2*>(bias + col);
#pragma unroll
            for (int rh = 0; rh < 2; rh++) {
                const size_t row = rowM0 + wm * 32 + mi * 16 + (lane >> 2) + rh * 8;
                float2 o;
                o.x = acc[mi][nf][rh * 2 + 0] + bv.x;
                o.y = acc[mi][nf][rh * 2 + 1] + bv.y;
                *reinterpret_cast<float2*>(C + row * DMODEL + col) = o;
            }
        }
    }
}

// ---------------------------------------------------------------------------
// Per-token attention; writes ctx directly as fp16 (A operand of final GEMM)
// ---------------------------------------------------------------------------
__global__ __launch_bounds__(256) void attn_kernel(
    const float* __restrict__ Q, const float* __restrict__ K,
    const float* __restrict__ V, __half* __restrict__ CH)
{
    const size_t base = (size_t)blockIdx.x * DMODEL;
    __shared__ float sq[DMODEL];
    __shared__ float sk[DMODEL];
    __shared__ float sv[DMODEL];
    __shared__ float sp[NHEAD][NHEAD];

    const int tid = threadIdx.x;
#pragma unroll
    for (int i = tid; i < DMODEL; i += 256) {
        sq[i] = Q[base + i];
        sk[i] = K[base + i];
        sv[i] = V[base + i];
    }
    __syncthreads();

    const int h = tid >> 4;
    const int g = tid & 15;
    const int rot = tid & 31;
    float s = 0.f;
#pragma unroll
    for (int dd = 0; dd < DHEAD; dd++) {
        const int d = (dd + rot) & (DHEAD - 1);
        s = fmaf(sq[h * DHEAD + d], sk[g * DHEAD + d], s);
    }
    s *= 0.125f;

    float m = s;
#pragma unroll
    for (int o = 8; o > 0; o >>= 1) m = fmaxf(m, __shfl_xor_sync(0xFFFFFFFFu, m, o, 16));
    const float e = __expf(s - m);
    float sum = e;
#pragma unroll
    for (int o = 8; o > 0; o >>= 1) sum += __shfl_xor_sync(0xFFFFFFFFu, sum, o, 16);
    sp[h][g] = e / sum;
    __syncthreads();

#pragma unroll
    for (int r = 0; r < 4; r++) {
        const int idx = tid + r * 256;
        const int hh  = idx >> 6;
        const int d   = idx & (DHEAD - 1);
        float a = 0.f;
#pragma unroll
        for (int gg = 0; gg < NHEAD; gg++)
            a = fmaf(sp[hh][gg], sv[gg * DHEAD + d], a);
        CH[base + idx] = __float2half_rn(a);
    }
}

// ---------------------------------------------------------------------------
extern "C" void kernel_launch(void* const* d_in, const int* in_sizes, int n_in,
                              void* d_out, int out_size)
{
    const float* x  = (const float*)d_in[0];
    const float* wq = (const float*)d_in[1];
    const float* bq = (const float*)d_in[2];
    const float* wk = (const float*)d_in[3];
    const float* bk = (const float*)d_in[4];
    const float* wv = (const float*)d_in[5];
    const float* bv = (const float*)d_in[6];
    const float* wo = (const float*)d_in[7];
    const float* bo = (const float*)d_in[8];
    float* out = (float*)d_out;

    float *q, *k, *v;
    cudaGetSymbolAddress((void**)&q, g_q);
    cudaGetSymbolAddress((void**)&k, g_k);
    cudaGetSymbolAddress((void**)&v, g_v);

    __half *xh, *ch, *whi, *wlo;
    cudaGetSymbolAddress((void**)&xh,  g_xh);
    cudaGetSymbolAddress((void**)&ch,  g_ch);
    cudaGetSymbolAddress((void**)&whi, g_whi);
    cudaGetSymbolAddress((void**)&wlo, g_wlo);

    cudaFuncSetAttribute(gemm_f16x2,
                         cudaFuncAttributeMaxDynamicSharedMemorySize, SMEM_DYN);

    const size_t WN = (size_t)DMODEL * DMODEL;
    const int nx4 = (TOKENS * DMODEL) / 4;
    const int nw4 = (int)(WN / 4);

    conv_f16<<<(nx4 + 255) / 256, 256>>>(x, xh, nx4);
    split_f16<<<(nw4 + 255) / 256, 256>>>(wq, whi + 0 * WN, wlo + 0 * WN, nw4);
    split_f16<<<(nw4 + 255) / 256, 256>>>(wk, whi + 1 * WN, wlo + 1 * WN, nw4);
    split_f16<<<(nw4 + 255) / 256, 256>>>(wv, whi + 2 * WN, wlo + 2 * WN, nw4);
    split_f16<<<(nw4 + 255) / 256, 256>>>(wo, whi + 3 * WN, wlo + 3 * WN, nw4);

    dim3 ggrid(DMODEL / 128, TOKENS / 128);   // (8, 256)
    gemm_f16x2<<<ggrid, 256, SMEM_DYN>>>(xh, whi + 0 * WN, wlo + 0 * WN, bq, q);
    gemm_f16x2<<<ggrid, 256, SMEM_DYN>>>(xh, whi + 1 * WN, wlo + 1 * WN, bk, k);
    gemm_f16x2<<<ggrid, 256, SMEM_DYN>>>(xh, whi + 2 * WN, wlo + 2 * WN, bv, v);

    attn_kernel<<<TOKENS, 256>>>(q, k, v, ch);

    gemm_f16x2<<<ggrid, 256, SMEM_DYN>>>(ch, whi + 3 * WN, wlo + 3 * WN, bo, out);
}